// round 7
// baseline (speedup 1.0000x reference)
#include <cuda_runtime.h>
#include <math.h>

// Problem constants
#define BATCH 8
#define TLEN 512
#define SLEN 512
#define EDIM 512
#define HDIM 1024
#define VDIM 32000
#define NL 6
#define MTOT (BATCH*TLEN)        // 4096
#define SCALE 0.7071067811865476f

// ---------------------------------------------------------------------------
// Scratch: single static device buffer (allocation-free rule).
// ---------------------------------------------------------------------------
__device__ float g_scratch[33570816];

#define OFF_EMB    0LL
#define OFF_XPAD   (OFF_EMB    + 2097152LL)
#define OFF_CONVED (OFF_XPAD   + 4210688LL)
#define OFF_GLU    (OFF_CONVED + 8388608LL)
#define OFF_COMB   (OFF_GLU    + 4194304LL)
#define OFF_ATTN   (OFF_COMB   + 2097152LL)
#define OFF_ATT    (OFF_ATTN   + 2097152LL)
#define OFF_COUT   (OFF_ATT    + 2097152LL)
#define OFF_WT     (OFF_COUT   + 2097152LL)

// ---------------------------------------------------------------------------
// embedded[m,:] = tok_emb[trg[m],:] + pos_emb[t,:]
// ---------------------------------------------------------------------------
__global__ void embed_kernel(const int* __restrict__ trg,
                             const float* __restrict__ tok,
                             const float* __restrict__ pos,
                             float* __restrict__ out) {
    int m = blockIdx.x;
    int t = m & (TLEN - 1);
    long long tokid = trg[m];
    const float4* te = (const float4*)(tok + tokid * EDIM);
    const float4* pe = (const float4*)(pos + (long long)t * EDIM);
    float4* o = (float4*)(out + (long long)m * EDIM);
    int i = threadIdx.x;  // 128 threads, EDIM/4 = 128
    float4 a = te[i], b = pe[i];
    o[i] = make_float4(a.x + b.x, a.y + b.y, a.z + b.z, a.w + b.w);
}

// Pad rows (t'=0,1 per batch) = 1.0f  (module quirk: pads with trg_pad_idx)
__global__ void pad_kernel(float* __restrict__ xpad) {
    int i = blockIdx.x * blockDim.x + threadIdx.x;  // 8*2*1024 = 16384
    int b = i >> 11;
    int r = i & 2047;
    xpad[(long long)b * 514 * 1024 + r] = 1.0f;
}

// conv_w[l]: (2H, H, K) -> wt: (K*H, 2H) with wt[kk*H+i][o] = w[o][i][kk]
// smem-tiled transpose: read coalesced over ik, write coalesced over o.
// FIX(R1): write must read the TRANSPOSED tile element tile[tx][r]
// (tile rows = o-offset, cols = ik-offset).
__global__ void transw_kernel(const float* __restrict__ w, float* __restrict__ wt) {
    __shared__ float tile[32][33];
    int ik0 = blockIdx.x * 32;  // over i*3+kk (3072)
    int o0  = blockIdx.y * 32;  // over o     (2048)
    for (int r = threadIdx.y; r < 32; r += 8)
        tile[r][threadIdx.x] = w[(long long)(o0 + r) * 3072 + ik0 + threadIdx.x];
    __syncthreads();
    for (int r = threadIdx.y; r < 32; r += 8) {
        int ikk = ik0 + r;
        int i = ikk / 3, kk = ikk - i * 3;
        long long kcat = (long long)kk * 1024 + i;
        wt[kcat * 2048 + o0 + threadIdx.x] = tile[threadIdx.x][r];
    }
}

// GLU: out[m,j] = conved[m,j] * sigmoid(conved[m,1024+j])
__global__ void glu_kernel(const float* __restrict__ conved, float* __restrict__ out) {
    long long idx = (long long)blockIdx.x * blockDim.x + threadIdx.x;  // 4,194,304
    long long m = idx >> 10;
    int j = (int)(idx & 1023);
    float a = conved[m * 2048 + j];
    float g = conved[m * 2048 + 1024 + j];
    out[idx] = a * (1.0f / (1.0f + expf(-g)));
}

// Row softmax over 512 cols (one block of 128 threads per row, float4 per thread)
__global__ void softmax_kernel(float* __restrict__ attn) {
    long long row = blockIdx.x;
    float4* p = (float4*)(attn + row * 512);
    float4 v = p[threadIdx.x];
    float mx = fmaxf(fmaxf(v.x, v.y), fmaxf(v.z, v.w));
    #pragma unroll
    for (int s = 16; s; s >>= 1) mx = fmaxf(mx, __shfl_xor_sync(0xffffffffu, mx, s));
    __shared__ float sm[4], ss[4];
    int w = threadIdx.x >> 5;
    if ((threadIdx.x & 31) == 0) sm[w] = mx;
    __syncthreads();
    mx = fmaxf(fmaxf(sm[0], sm[1]), fmaxf(sm[2], sm[3]));
    v.x = expf(v.x - mx); v.y = expf(v.y - mx);
    v.z = expf(v.z - mx); v.w = expf(v.w - mx);
    float sum = v.x + v.y + v.z + v.w;
    #pragma unroll
    for (int s = 16; s; s >>= 1) sum += __shfl_xor_sync(0xffffffffu, sum, s);
    if ((threadIdx.x & 31) == 0) ss[w] = sum;
    __syncthreads();
    float inv = 1.0f / (ss[0] + ss[1] + ss[2] + ss[3]);
    v.x *= inv; v.y *= inv; v.z *= inv; v.w *= inv;
    p[threadIdx.x] = v;
}

// ---------------------------------------------------------------------------
// Generic tiled fp32 GEMM: C = epi(A @ B)
//   128x128 block tile, BK=8, 256 threads, 8x8 per-thread microtile.
//   AMAP: 0 = A row m at m*lda
//         1 = xpad conv map   (row base (m+2b)*H, 3072 contiguous = tokens t-2..t)
//         2 = xpad token map  (row base (m+2b+2)*H)
//   CMAP: 0 = C row m at m*N ; 1 = xpad interior map ((m+2b+2)*H)
//   EPI : 0 = +bias
//         1 = (acc + bias + add1[m,n]) * SCALE                      (combined)
//         2 = ((acc + bias + add1[m,n]) * SCALE + C_old) * SCALE    (residual->xpad)
//         3 = plain store
//   BTRANS: B operand is (N x K) row-major, K contiguous (A @ B^T)
// ---------------------------------------------------------------------------
template<int AMAP, int CMAP, int EPI, bool BTRANS>
__global__ __launch_bounds__(256) void gemm128(
    const float* __restrict__ A, const float* __restrict__ Bm,
    const float* __restrict__ bias, const float* __restrict__ add1,
    float* __restrict__ C, int M, int N, int Kd, int lda, int ldb,
    long long batA, long long batB, long long batC)
{
    A  += (long long)blockIdx.z * batA;
    Bm += (long long)blockIdx.z * batB;
    C  += (long long)blockIdx.z * batC;

    __shared__ float As[8][128];
    __shared__ float Bs[8][128];
    const int tid = threadIdx.x;
    const int m0 = blockIdx.y * 128, n0 = blockIdx.x * 128;

    const int a_m  = tid >> 1;
    const int a_k4 = (tid & 1) * 4;
    const int b_k  = tid >> 5;
    const int b_n4 = (tid & 31) * 4;

    const int am = m0 + a_m;
    long long arow;
    if (AMAP == 0)      arow = (long long)am * lda;
    else if (AMAP == 1) arow = (long long)(am + 2 * (am >> 9)) * HDIM;
    else                arow = (long long)(am + 2 * (am >> 9) + 2) * HDIM;

    long long brow;
    if (!BTRANS) brow = (long long)b_k * ldb + n0 + b_n4;
    else         brow = (long long)(n0 + a_m) * ldb + a_k4;

    float acc[8][8];
    #pragma unroll
    for (int i = 0; i < 8; i++)
        #pragma unroll
        for (int j = 0; j < 8; j++) acc[i][j] = 0.0f;

    const int tm = (tid >> 4) * 8;
    const int tn = (tid & 15) * 8;

    for (int k0 = 0; k0 < Kd; k0 += 8) {
        float4 av = *(const float4*)(A + arow + k0 + a_k4);
        float4 bv;
        if (!BTRANS) bv = *(const float4*)(Bm + brow + (long long)k0 * ldb);
        else         bv = *(const float4*)(Bm + brow + k0);
        __syncthreads();
        As[a_k4 + 0][a_m] = av.x;
        As[a_k4 + 1][a_m] = av.y;
        As[a_k4 + 2][a_m] = av.z;
        As[a_k4 + 3][a_m] = av.w;
        if (!BTRANS) {
            *(float4*)(&Bs[b_k][b_n4]) = bv;
        } else {
            Bs[a_k4 + 0][a_m] = bv.x;
            Bs[a_k4 + 1][a_m] = bv.y;
            Bs[a_k4 + 2][a_m] = bv.z;
            Bs[a_k4 + 3][a_m] = bv.w;
        }
        __syncthreads();
        #pragma unroll
        for (int kk = 0; kk < 8; kk++) {
            float af[8], bf[8];
            *(float4*)(af)     = *(const float4*)(&As[kk][tm]);
            *(float4*)(af + 4) = *(const float4*)(&As[kk][tm + 4]);
            *(float4*)(bf)     = *(const float4*)(&Bs[kk][tn]);
            *(float4*)(bf + 4) = *(const float4*)(&Bs[kk][tn + 4]);
            #pragma unroll
            for (int i = 0; i < 8; i++)
                #pragma unroll
                for (int j = 0; j < 8; j++)
                    acc[i][j] = fmaf(af[i], bf[j], acc[i][j]);
        }
    }

    #pragma unroll
    for (int i = 0; i < 8; i++) {
        int m = m0 + tm + i;
        long long coff;
        if (CMAP == 0) coff = (long long)m * N + n0 + tn;
        else           coff = (long long)(m + 2 * (m >> 9) + 2) * HDIM + n0 + tn;
        #pragma unroll
        for (int j = 0; j < 8; j++) {
            float v = acc[i][j];
            int n = n0 + tn + j;
            if (EPI == 0)      v += bias[n];
            else if (EPI == 1) v = (v + bias[n] + add1[(long long)m * N + n]) * SCALE;
            else if (EPI == 2) v = ((v + bias[n] + add1[(long long)m * N + n]) * SCALE
                                    + C[coff + j]) * SCALE;
            C[coff + j] = v;
        }
    }
}

// ---------------------------------------------------------------------------
extern "C" void kernel_launch(void* const* d_in, const int* in_sizes, int n_in,
                              void* d_out, int out_size) {
    const int*   trg         = (const int*)d_in[0];
    const float* enc_conved  = (const float*)d_in[1];
    const float* enc_comb    = (const float*)d_in[2];
    const float* tok_emb     = (const float*)d_in[3];
    const float* pos_emb     = (const float*)d_in[4];
    const float* emb2hid_w   = (const float*)d_in[5];
    const float* emb2hid_b   = (const float*)d_in[6];
    const float* hid2emb_w   = (const float*)d_in[7];
    const float* hid2emb_b   = (const float*)d_in[8];
    const float* attn_h2e_w  = (const float*)d_in[9];
    const float* attn_h2e_b  = (const float*)d_in[10];
    const float* attn_e2h_w  = (const float*)d_in[11];
    const float* attn_e2h_b  = (const float*)d_in[12];
    const float* fc_w        = (const float*)d_in[13];
    const float* fc_b        = (const float*)d_in[14];
    const float* conv_w      = (const float*)d_in[15];
    const float* conv_b      = (const float*)d_in[16];
    float* out = (float*)d_out;

    float* S = nullptr;
    cudaGetSymbolAddress((void**)&S, g_scratch);
    float* emb    = S + OFF_EMB;
    float* xpad   = S + OFF_XPAD;
    float* conved = S + OFF_CONVED;
    float* glu    = S + OFF_GLU;
    float* comb   = S + OFF_COMB;
    float* attn   = S + OFF_ATTN;
    float* att    = S + OFF_ATT;
    float* cout_  = S + OFF_COUT;
    float* wt     = S + OFF_WT;

    const long long TE = (long long)TLEN * EDIM;   // 262144
    const long long TS = (long long)TLEN * SLEN;   // 262144

    // embeddings + pad rows
    embed_kernel<<<MTOT, 128>>>(trg, tok_emb, pos_emb, emb);
    pad_kernel<<<16, 1024>>>(xpad);

    // conv_input = embedded @ emb2hid_w + b   -> xpad interior (token rows)
    gemm128<0, 1, 0, false><<<dim3(8, 32, 1), 256>>>(
        emb, emb2hid_w, emb2hid_b, nullptr, xpad,
        MTOT, HDIM, EDIM, EDIM, HDIM, 0, 0, 0);

    for (int l = 0; l < NL; l++) {
        // permute conv weights: (2H,H,K) -> (3H, 2H)
        transw_kernel<<<dim3(96, 64), dim3(32, 8)>>>(
            conv_w + (long long)l * 2048 * 1024 * 3, wt);

        // conv as GEMM: A rows = 3 consecutive padded token rows (3072 contiguous)
        gemm128<1, 0, 0, false><<<dim3(16, 32, 1), 256>>>(
            xpad, wt, conv_b + l * 2048, nullptr, conved,
            MTOT, 2 * HDIM, 3 * HDIM, HDIM, 2 * HDIM, 0, 0, 0);

        // GLU
        glu_kernel<<<4096, 1024>>>(conved, glu);

        // combined = (glu @ attn_hid2emb_w + b + embedded) * scale
        gemm128<0, 0, 1, false><<<dim3(4, 32, 1), 256>>>(
            glu, attn_h2e_w, attn_h2e_b, emb, comb,
            MTOT, EDIM, HDIM, HDIM, EDIM, 0, 0, 0);

        // energy = combined @ enc_conved^T  (batched NT)
        gemm128<0, 0, 3, true><<<dim3(4, 4, BATCH), 256>>>(
            comb, enc_conved, nullptr, nullptr, attn,
            TLEN, SLEN, EDIM, EDIM, EDIM, TE, TE, TS);

        softmax_kernel<<<MTOT, 128>>>(attn);

        // attended = attn @ enc_combined  (batched NN)
        gemm128<0, 0, 3, false><<<dim3(4, 4, BATCH), 256>>>(
            attn, enc_comb, nullptr, nullptr, att,
            TLEN, EDIM, SLEN, SLEN, EDIM, TS, TE, TE);

        // conv_input = ((glu + attended@W + b)*scale + conv_input)*scale -> xpad
        gemm128<0, 1, 2, false><<<dim3(8, 32, 1), 256>>>(
            att, attn_e2h_w, attn_e2h_b, glu, xpad,
            MTOT, HDIM, EDIM, EDIM, HDIM, 0, 0, 0);
    }

    // conv_output = conv_input @ hid2emb_w + b
    gemm128<2, 0, 0, false><<<dim3(4, 32, 1), 256>>>(
        xpad, hid2emb_w, hid2emb_b, nullptr, cout_,
        MTOT, EDIM, HDIM, HDIM, EDIM, 0, 0, 0);

    // logits = conv_output @ fc_out_w + b
    gemm128<0, 0, 0, false><<<dim3(250, 32, 1), 256>>>(
        cout_, fc_w, fc_b, nullptr, out,
        MTOT, VDIM, EDIM, EDIM, VDIM, 0, 0, 0);
}

// round 11
// speedup vs baseline: 2.3502x; 2.3502x over previous
#include <cuda_runtime.h>
#include <cuda_bf16.h>
#include <cstdint>
#include <math.h>

#define BATCH 8
#define TLEN 512
#define EDIM 512
#define HDIM 1024
#define VDIM 32000
#define NL 6
#define MTOT (BATCH*TLEN)
#define SCALE 0.7071067811865476f

// ===========================================================================
// Scratch carve-out (bytes)
// ===========================================================================
constexpr unsigned long long
 oEMBF  = 0ull,
 oXPADF = oEMBF  + 8388608ull,
 oCONVF = oXPADF + 16842752ull,
 oGLUF  = oCONVF + 33554432ull,
 oATTNF = oGLUF  + 16777216ull,
 oEMBH  = oATTNF + 8388608ull,
 oEMBL  = oEMBH  + 4194304ull,
 oXPADH = oEMBL  + 4194304ull,
 oXPADL = oXPADH + 8421376ull,
 oGLUH  = oXPADL + 8421376ull,
 oGLUL  = oGLUH  + 8388608ull,
 oCOMBH = oGLUL  + 8388608ull,
 oCOMBL = oCOMBH + 4194304ull,
 oATTNH = oCOMBL + 4194304ull,
 oATTNL = oATTNH + 4194304ull,
 oATTH  = oATTNL + 4194304ull,
 oATTL  = oATTH  + 4194304ull,
 oCOUTH = oATTL  + 4194304ull,
 oCOUTL = oCOUTH + 4194304ull,
 oWTH   = oCOUTL + 4194304ull,
 oWTL   = oWTH   + 12582912ull,
 oW1H   = oWTL   + 12582912ull,
 oW1L   = oW1H   + 1048576ull,
 oW2H   = oW1L   + 1048576ull,
 oW2L   = oW2H   + 1048576ull,
 oW3H   = oW2L   + 1048576ull,
 oW3L   = oW3H   + 1048576ull,
 oW4H   = oW3L   + 1048576ull,
 oW4L   = oW4H   + 1048576ull,
 oWFCH  = oW4L   + 1048576ull,
 oWFCL  = oWFCH  + 32768000ull,
 oENCVH = oWFCL  + 32768000ull,
 oENCVL = oENCVH + 4194304ull,
 oENCTH = oENCVL + 4194304ull,
 oENCTL = oENCTH + 4194304ull,
 G_TOTAL = oENCTL + 4194304ull;

__device__ __align__(1024) unsigned char g_mem[G_TOTAL];

// ===========================================================================
// PTX helpers (arch-agnostic: cp.async + ldmatrix + mma.sync bf16)
// ===========================================================================
__device__ __forceinline__ uint32_t smem_u32(const void* p) {
    uint32_t a;
    asm("{ .reg .u64 t; cvta.to.shared.u64 t, %1; cvt.u32.u64 %0, t; }" : "=r"(a) : "l"(p));
    return a;
}
#define CP16(dst, src) asm volatile("cp.async.cg.shared.global [%0], [%1], 16;" :: "r"(dst), "l"(src))
#define CP_COMMIT()    asm volatile("cp.async.commit_group;" ::: "memory")
template<int N> __device__ __forceinline__ void cp_wait() {
    asm volatile("cp.async.wait_group %0;" :: "n"(N) : "memory");
}
__device__ __forceinline__ void ldsm4(uint32_t* d, uint32_t a) {
    asm volatile("ldmatrix.sync.aligned.m8n8.x4.shared.b16 {%0,%1,%2,%3}, [%4];"
        : "=r"(d[0]), "=r"(d[1]), "=r"(d[2]), "=r"(d[3]) : "r"(a));
}
__device__ __forceinline__ void mma16816(float* c, const uint32_t* a, const uint32_t* b) {
    asm volatile("mma.sync.aligned.m16n8k16.row.col.f32.bf16.bf16.f32 "
        "{%0,%1,%2,%3}, {%4,%5,%6,%7}, {%8,%9}, {%0,%1,%2,%3};"
        : "+f"(c[0]), "+f"(c[1]), "+f"(c[2]), "+f"(c[3])
        : "r"(a[0]), "r"(a[1]), "r"(a[2]), "r"(a[3]), "r"(b[0]), "r"(b[1]));
}

__device__ __forceinline__ void store_split4(__nv_bfloat16* ph, __nv_bfloat16* pl, float4 v) {
    __nv_bfloat16 h0 = __float2bfloat16(v.x), h1 = __float2bfloat16(v.y);
    __nv_bfloat16 h2 = __float2bfloat16(v.z), h3 = __float2bfloat16(v.w);
    __nv_bfloat162 a; a.x = h0; a.y = h1;
    __nv_bfloat162 b; b.x = h2; b.y = h3;
    *(__nv_bfloat162*)(ph) = a; *(__nv_bfloat162*)(ph + 2) = b;
    __nv_bfloat162 c, d;
    c.x = __float2bfloat16(v.x - __bfloat162float(h0));
    c.y = __float2bfloat16(v.y - __bfloat162float(h1));
    d.x = __float2bfloat16(v.z - __bfloat162float(h2));
    d.y = __float2bfloat16(v.w - __bfloat162float(h3));
    *(__nv_bfloat162*)(pl) = c; *(__nv_bfloat162*)(pl + 2) = d;
}
__device__ __forceinline__ void store_split2(__nv_bfloat16* ph, __nv_bfloat16* pl,
                                             float x, float y) {
    __nv_bfloat16 h0 = __float2bfloat16(x), h1 = __float2bfloat16(y);
    __nv_bfloat162 a; a.x = h0; a.y = h1;
    *(__nv_bfloat162*)(ph) = a;
    __nv_bfloat162 c;
    c.x = __float2bfloat16(x - __bfloat162float(h0));
    c.y = __float2bfloat16(y - __bfloat162float(h1));
    *(__nv_bfloat162*)(pl) = c;
}

// ===========================================================================
// Elementwise / prep kernels
// ===========================================================================
__global__ void embed_kernel(const int* __restrict__ trg, const float* __restrict__ tok,
                             const float* __restrict__ pos, float* __restrict__ out,
                             __nv_bfloat16* __restrict__ oh, __nv_bfloat16* __restrict__ ol) {
    int m = blockIdx.x, t = m & (TLEN - 1), i = threadIdx.x;
    long long tokid = trg[m];
    float4 a = ((const float4*)(tok + tokid * EDIM))[i];
    float4 b = ((const float4*)(pos + (long long)t * EDIM))[i];
    float4 v = make_float4(a.x + b.x, a.y + b.y, a.z + b.z, a.w + b.w);
    ((float4*)(out + (long long)m * EDIM))[i] = v;
    long long o = (long long)m * EDIM + i * 4;
    store_split4(oh + o, ol + o, v);
}

__global__ void pad_kernel(float* __restrict__ xp, __nv_bfloat16* __restrict__ xh,
                           __nv_bfloat16* __restrict__ xl) {
    int i = blockIdx.x * blockDim.x + threadIdx.x;
    int b = i >> 11, r = i & 2047;
    long long o = (long long)b * 514 * 1024 + r;
    xp[o] = 1.0f; xh[o] = __float2bfloat16(1.0f); xl[o] = __float2bfloat16(0.0f);
}

__global__ void glu_kernel(const float* __restrict__ conved, float* __restrict__ out,
                           __nv_bfloat16* __restrict__ oh, __nv_bfloat16* __restrict__ ol) {
    long long idx = (long long)blockIdx.x * blockDim.x + threadIdx.x;
    long long m = idx >> 10;
    int j = (int)(idx & 1023);
    float a = conved[m * 2048 + j];
    float g = conved[m * 2048 + 1024 + j];
    float v = a * (1.0f / (1.0f + expf(-g)));
    out[idx] = v;
    __nv_bfloat16 h = __float2bfloat16(v);
    oh[idx] = h;
    ol[idx] = __float2bfloat16(v - __bfloat162float(h));
}

__global__ void softmax_kernel(const float* __restrict__ attn,
                               __nv_bfloat16* __restrict__ oh, __nv_bfloat16* __restrict__ ol) {
    long long row = blockIdx.x;
    const float4* p = (const float4*)(attn + row * 512);
    float4 v = p[threadIdx.x];
    float mx = fmaxf(fmaxf(v.x, v.y), fmaxf(v.z, v.w));
    #pragma unroll
    for (int s = 16; s; s >>= 1) mx = fmaxf(mx, __shfl_xor_sync(0xffffffffu, mx, s));
    __shared__ float sm[4], ss[4];
    int w = threadIdx.x >> 5;
    if ((threadIdx.x & 31) == 0) sm[w] = mx;
    __syncthreads();
    mx = fmaxf(fmaxf(sm[0], sm[1]), fmaxf(sm[2], sm[3]));
    v.x = expf(v.x - mx); v.y = expf(v.y - mx);
    v.z = expf(v.z - mx); v.w = expf(v.w - mx);
    float sum = v.x + v.y + v.z + v.w;
    #pragma unroll
    for (int s = 16; s; s >>= 1) sum += __shfl_xor_sync(0xffffffffu, sum, s);
    if ((threadIdx.x & 31) == 0) ss[w] = sum;
    __syncthreads();
    float inv = 1.0f / (ss[0] + ss[1] + ss[2] + ss[3]);
    v.x *= inv; v.y *= inv; v.z *= inv; v.w *= inv;
    long long o = row * 512 + threadIdx.x * 4;
    store_split4(oh + o, ol + o, v);
}

__global__ void split_kernel(const float* __restrict__ in, __nv_bfloat16* __restrict__ oh,
                             __nv_bfloat16* __restrict__ ol, long long n) {
    long long idx = (long long)blockIdx.x * blockDim.x + threadIdx.x;
    if (idx >= n) return;
    float v = in[idx];
    __nv_bfloat16 h = __float2bfloat16(v);
    oh[idx] = h;
    ol[idx] = __float2bfloat16(v - __bfloat162float(h));
}

// fp32 (R,C) -> bf16 hi/lo (C,R), batched by blockIdx.z
__global__ void transpose_split_kernel(const float* __restrict__ in,
                                       __nv_bfloat16* __restrict__ oh,
                                       __nv_bfloat16* __restrict__ ol,
                                       int R, int C, long long bat) {
    __shared__ float t[32][33];
    in += blockIdx.z * bat; oh += blockIdx.z * bat; ol += blockIdx.z * bat;
    int c0 = blockIdx.x * 32, r0 = blockIdx.y * 32;
    int tx = threadIdx.x, ty = threadIdx.y;
    for (int ry = ty; ry < 32; ry += 8)
        t[ry][tx] = in[(long long)(r0 + ry) * C + c0 + tx];
    __syncthreads();
    for (int ry = ty; ry < 32; ry += 8) {
        float v = t[tx][ry];
        long long o = (long long)(c0 + ry) * R + r0 + tx;
        __nv_bfloat16 h = __float2bfloat16(v);
        oh[o] = h;
        ol[o] = __float2bfloat16(v - __bfloat162float(h));
    }
}

// conv_w layer (2H,H,K): row o contiguous (i,kk); out[o][kk*1024+i], split.
__global__ void convw_split_kernel(const float* __restrict__ w,
                                   __nv_bfloat16* __restrict__ oh,
                                   __nv_bfloat16* __restrict__ ol) {
    __shared__ float row[3072];
    long long o = blockIdx.x;
    for (int x = threadIdx.x; x < 3072; x += 256) row[x] = w[o * 3072 + x];
    __syncthreads();
    for (int y = threadIdx.x; y < 3072; y += 256) {
        int i = y & 1023, kk = y >> 10;
        float v = row[i * 3 + kk];
        __nv_bfloat16 h = __float2bfloat16(v);
        oh[o * 3072 + y] = h;
        ol[o * 3072 + y] = __float2bfloat16(v - __bfloat162float(h));
    }
}

// ===========================================================================
// mma.sync bf16-split GEMM: C(128x128 tile) = epi( A(M,K) @ B(N,K)^T )
//   Ah*Bh + Ah*Bl + Al*Bh, fp32 register accumulation.
//   256 threads, 8 warps (2x4 -> 64x32 per warp), BK=32, 2-stage cp.async.
//   Smem per operand: [128 rows][40 bf16] (8-elem pad -> conflict-free ldmatrix).
//   AMAP: 0 row m*lda ; 1 conv map (m+2b)*1024 ; 2 token map (m+2b+2)*1024
//   CMAP: 0 m*N ; 1 xpad interior
//   EPI : 0 +bias ; 1 (acc+b+add1)*S ; 2 ((acc+b+add1)*S+Cold)*S ; 3 plain
//   OUT : 0 fp32 ; 1 fp32+split ; 2 split only
// ===========================================================================
constexpr int OPB   = 128 * 40 * 2;   // 10240 bytes per operand
constexpr int STAGE = 4 * OPB;        // 40960
constexpr int GSMEM = 2 * STAGE;      // 81920

template<int AMAP, int CMAP, int EPI, int OUT>
__global__ __launch_bounds__(256, 1) void tgemm(
    const __nv_bfloat16* __restrict__ Ahi, const __nv_bfloat16* __restrict__ Alo,
    const __nv_bfloat16* __restrict__ Bhi, const __nv_bfloat16* __restrict__ Blo,
    const float* __restrict__ bias, const float* __restrict__ add1,
    float* __restrict__ C, __nv_bfloat16* __restrict__ Chi, __nv_bfloat16* __restrict__ Clo,
    int N, int Kd, int lda, long long batA, long long batB, long long batC)
{
    extern __shared__ __align__(128) char smem[];
    const uint32_t sb = smem_u32(smem);
    const int tid = threadIdx.x;
    const int lane = tid & 31, wid = tid >> 5;
    const int m0 = blockIdx.y * 128, n0 = blockIdx.x * 128;
    const int wm = (wid >> 2) * 64, wn = (wid & 3) * 32;
    {
        long long z = blockIdx.z;
        Ahi += z * batA; Alo += z * batA;
        Bhi += z * batB; Blo += z * batB;
        if (OUT != 2) C += z * batC;
        if (OUT >= 1) { Chi += z * batC; Clo += z * batC; }
    }

    float acc[4][4][4];
    #pragma unroll
    for (int a = 0; a < 4; a++)
        #pragma unroll
        for (int b = 0; b < 4; b++)
            #pragma unroll
            for (int c = 0; c < 4; c++) acc[a][b][c] = 0.0f;

    const int nch = Kd >> 5;   // BK = 32

    // ---- async loader for chunk j into stage j&1 ----
    auto load_chunk = [&](int j) {
        uint32_t st = sb + (j & 1) * STAGE;
        int k0 = j * 32;
        #pragma unroll
        for (int i2 = 0; i2 < 2; i2++) {
            int sidx = i2 * 256 + tid;          // 512 segments of 16B per operand
            int r = sidx >> 2, sg = sidx & 3;
            uint32_t soff = r * 80 + sg * 16;
            int gm = m0 + r;
            long long ab;
            if (AMAP == 0)      ab = (long long)gm * lda;
            else if (AMAP == 1) ab = (long long)(gm + 2 * (gm >> 9)) * 1024;
            else                ab = (long long)(gm + 2 * (gm >> 9) + 2) * 1024;
            long long aoff = (ab + k0) * 2 + sg * 16;
            CP16(st + soff,           (const char*)Ahi + aoff);
            CP16(st + OPB + soff,     (const char*)Alo + aoff);
            long long bb = ((long long)(n0 + r) * Kd + k0) * 2 + sg * 16;
            CP16(st + 2 * OPB + soff, (const char*)Bhi + bb);
            CP16(st + 3 * OPB + soff, (const char*)Blo + bb);
        }
        CP_COMMIT();
    };

    load_chunk(0);
    for (int j = 0; j < nch; j++) {
        if (j + 1 < nch) { load_chunk(j + 1); cp_wait<1>(); }
        else             { cp_wait<0>(); }
        __syncthreads();

        uint32_t sA  = sb + (j & 1) * STAGE;
        uint32_t sAl = sA + OPB, sB = sA + 2 * OPB, sBl = sA + 3 * OPB;
        #pragma unroll
        for (int kc = 0; kc < 32; kc += 16) {
            uint32_t aH[4][4], aL[4][4], bH[4][2], bL[4][2];
            #pragma unroll
            for (int mt = 0; mt < 4; mt++) {
                uint32_t ro = (uint32_t)(wm + mt * 16 + (lane & 15)) * 80
                            + (kc + (lane >> 4) * 8) * 2;
                ldsm4(aH[mt], sA + ro);
                ldsm4(aL[mt], sAl + ro);
            }
            #pragma unroll
            for (int bt = 0; bt < 2; bt++) {
                uint32_t ro = (uint32_t)(wn + bt * 16 + (lane >> 4) * 8 + (lane & 7)) * 80
                            + (kc + ((lane >> 3) & 1) * 8) * 2;
                uint32_t t4[4];
                ldsm4(t4, sB + ro);
                bH[2 * bt][0] = t4[0]; bH[2 * bt][1] = t4[1];
                bH[2 * bt + 1][0] = t4[2]; bH[2 * bt + 1][1] = t4[3];
                ldsm4(t4, sBl + ro);
                bL[2 * bt][0] = t4[0]; bL[2 * bt][1] = t4[1];
                bL[2 * bt + 1][0] = t4[2]; bL[2 * bt + 1][1] = t4[3];
            }
            #pragma unroll
            for (int mt = 0; mt < 4; mt++)
                #pragma unroll
                for (int nt = 0; nt < 4; nt++)
                    mma16816(acc[mt][nt], aH[mt], bH[nt]);
            #pragma unroll
            for (int mt = 0; mt < 4; mt++)
                #pragma unroll
                for (int nt = 0; nt < 4; nt++)
                    mma16816(acc[mt][nt], aH[mt], bL[nt]);
            #pragma unroll
            for (int mt = 0; mt < 4; mt++)
                #pragma unroll
                for (int nt = 0; nt < 4; nt++)
                    mma16816(acc[mt][nt], aL[mt], bH[nt]);
        }
        __syncthreads();
    }

    // ---- epilogue: fragment layout c0,c1 = row lane/4, c2,c3 = row+8 ----
    const int rq = lane >> 2, cq = (lane & 3) * 2;
    #pragma unroll
    for (int mt = 0; mt < 4; mt++) {
        #pragma unroll
        for (int h = 0; h < 2; h++) {
            int m = m0 + wm + mt * 16 + h * 8 + rq;
            long long crow;
            if (CMAP == 0) crow = (long long)m * N;
            else           crow = (long long)(m + 2 * (m >> 9) + 2) * 1024;
            long long arow = (long long)m * N;
            #pragma unroll
            for (int nt = 0; nt < 4; nt++) {
                int n = n0 + wn + nt * 8 + cq;
                float x = acc[mt][nt][h * 2 + 0];
                float y = acc[mt][nt][h * 2 + 1];
                if (EPI != 3) {
                    float2 b2 = *(const float2*)(bias + n);
                    x += b2.x; y += b2.y;
                }
                if (EPI == 1 || EPI == 2) {
                    float2 a2 = *(const float2*)(add1 + arow + n);
                    x = (x + a2.x) * SCALE; y = (y + a2.y) * SCALE;
                }
                if (EPI == 2) {
                    float2 c2v = *(const float2*)(C + crow + n);
                    x = (x + c2v.x) * SCALE; y = (y + c2v.y) * SCALE;
                }
                if (OUT != 2) { float2 o2; o2.x = x; o2.y = y;
                                *(float2*)(C + crow + n) = o2; }
                if (OUT >= 1) store_split2(Chi + crow + n, Clo + crow + n, x, y);
            }
        }
    }
}

// ===========================================================================
extern "C" void kernel_launch(void* const* d_in, const int* in_sizes, int n_in,
                              void* d_out, int out_size) {
    const int*   trg        = (const int*)d_in[0];
    const float* enc_conved = (const float*)d_in[1];
    const float* enc_comb   = (const float*)d_in[2];
    const float* tok_emb    = (const float*)d_in[3];
    const float* pos_emb    = (const float*)d_in[4];
    const float* emb2hid_w  = (const float*)d_in[5];
    const float* emb2hid_b  = (const float*)d_in[6];
    const float* hid2emb_w  = (const float*)d_in[7];
    const float* hid2emb_b  = (const float*)d_in[8];
    const float* attn_h2e_w = (const float*)d_in[9];
    const float* attn_h2e_b = (const float*)d_in[10];
    const float* attn_e2h_w = (const float*)d_in[11];
    const float* attn_e2h_b = (const float*)d_in[12];
    const float* fc_w       = (const float*)d_in[13];
    const float* fc_b       = (const float*)d_in[14];
    const float* conv_w     = (const float*)d_in[15];
    const float* conv_b     = (const float*)d_in[16];
    float* out = (float*)d_out;

    unsigned char* base = nullptr;
    cudaGetSymbolAddress((void**)&base, g_mem);
#define F32P(o) ((float*)(base + (o)))
#define BFP(o)  ((__nv_bfloat16*)(base + (o)))
    float *embF = F32P(oEMBF), *xpadF = F32P(oXPADF), *convF = F32P(oCONVF);
    float *gluF = F32P(oGLUF), *attnF = F32P(oATTNF);
    __nv_bfloat16 *embH = BFP(oEMBH),  *embL = BFP(oEMBL);
    __nv_bfloat16 *xpH  = BFP(oXPADH), *xpL  = BFP(oXPADL);
    __nv_bfloat16 *glH  = BFP(oGLUH),  *glL  = BFP(oGLUL);
    __nv_bfloat16 *cbH  = BFP(oCOMBH), *cbL  = BFP(oCOMBL);
    __nv_bfloat16 *atH  = BFP(oATTNH), *atL  = BFP(oATTNL);
    __nv_bfloat16 *adH  = BFP(oATTH),  *adL  = BFP(oATTL);
    __nv_bfloat16 *coH  = BFP(oCOUTH), *coL  = BFP(oCOUTL);
    __nv_bfloat16 *wtH  = BFP(oWTH),   *wtL  = BFP(oWTL);
    __nv_bfloat16 *w1H  = BFP(oW1H),   *w1L  = BFP(oW1L);
    __nv_bfloat16 *w2H  = BFP(oW2H),   *w2L  = BFP(oW2L);
    __nv_bfloat16 *w3H  = BFP(oW3H),   *w3L  = BFP(oW3L);
    __nv_bfloat16 *w4H  = BFP(oW4H),   *w4L  = BFP(oW4L);
    __nv_bfloat16 *wfH  = BFP(oWFCH),  *wfL  = BFP(oWFCL);
    __nv_bfloat16 *evH  = BFP(oENCVH), *evL  = BFP(oENCVL);
    __nv_bfloat16 *etH  = BFP(oENCTH), *etL  = BFP(oENCTL);

    cudaFuncSetAttribute(tgemm<0,1,0,1>, cudaFuncAttributeMaxDynamicSharedMemorySize, GSMEM);
    cudaFuncSetAttribute(tgemm<1,0,0,0>, cudaFuncAttributeMaxDynamicSharedMemorySize, GSMEM);
    cudaFuncSetAttribute(tgemm<0,0,1,2>, cudaFuncAttributeMaxDynamicSharedMemorySize, GSMEM);
    cudaFuncSetAttribute(tgemm<0,0,3,0>, cudaFuncAttributeMaxDynamicSharedMemorySize, GSMEM);
    cudaFuncSetAttribute(tgemm<0,0,3,2>, cudaFuncAttributeMaxDynamicSharedMemorySize, GSMEM);
    cudaFuncSetAttribute(tgemm<0,1,2,1>, cudaFuncAttributeMaxDynamicSharedMemorySize, GSMEM);
    cudaFuncSetAttribute(tgemm<2,0,0,2>, cudaFuncAttributeMaxDynamicSharedMemorySize, GSMEM);
    cudaFuncSetAttribute(tgemm<0,0,0,0>, cudaFuncAttributeMaxDynamicSharedMemorySize, GSMEM);

    const long long TS = (long long)TLEN * TLEN;  // 262144

    // ---- one-time prep ----
    embed_kernel<<<MTOT, 128>>>(trg, tok_emb, pos_emb, embF, embH, embL);
    pad_kernel<<<16, 1024>>>(xpadF, xpH, xpL);
    transpose_split_kernel<<<dim3(32, 16), dim3(32, 8)>>>(emb2hid_w, w1H, w1L, 512, 1024, 0);
    transpose_split_kernel<<<dim3(16, 32), dim3(32, 8)>>>(attn_h2e_w, w2H, w2L, 1024, 512, 0);
    transpose_split_kernel<<<dim3(32, 16), dim3(32, 8)>>>(attn_e2h_w, w3H, w3L, 512, 1024, 0);
    transpose_split_kernel<<<dim3(16, 32), dim3(32, 8)>>>(hid2emb_w, w4H, w4L, 1024, 512, 0);
    transpose_split_kernel<<<dim3(1000, 16), dim3(32, 8)>>>(fc_w, wfH, wfL, 512, 32000, 0);
    transpose_split_kernel<<<dim3(16, 16, 8), dim3(32, 8)>>>(enc_comb, etH, etL, 512, 512, TS);
    split_kernel<<<8192, 256>>>(enc_conved, evH, evL, 2097152LL);

    // conv_input = embedded @ emb2hid + b -> xpad (fp32 + split)
    tgemm<0,1,0,1><<<dim3(8, 32), 256, GSMEM>>>(
        embH, embL, w1H, w1L, emb2hid_b, nullptr, xpadF, xpH, xpL,
        1024, 512, 512, 0, 0, 0);

    for (int l = 0; l < NL; l++) {
        convw_split_kernel<<<2048, 256>>>(conv_w + (long long)l * 2048 * 3072, wtH, wtL);

        // conved = xpad(conv map) @ wt^T + b   (K=3072), fp32 only
        tgemm<1,0,0,0><<<dim3(16, 32), 256, GSMEM>>>(
            xpH, xpL, wtH, wtL, conv_b + l * 2048, nullptr, convF, nullptr, nullptr,
            2048, 3072, 1024, 0, 0, 0);

        glu_kernel<<<4096, 1024>>>(convF, gluF, glH, glL);

        // combined = (glu @ h2e + b + emb)*scale, split only
        tgemm<0,0,1,2><<<dim3(4, 32), 256, GSMEM>>>(
            glH, glL, w2H, w2L, attn_h2e_b, embF, nullptr, cbH, cbL,
            512, 1024, 1024, 0, 0, 0);

        // energy = combined @ enc_conved^T (batched), fp32 only
        tgemm<0,0,3,0><<<dim3(4, 4, 8), 256, GSMEM>>>(
            cbH, cbL, evH, evL, nullptr, nullptr, attnF, nullptr, nullptr,
            512, 512, 512, TS, TS, TS);

        softmax_kernel<<<MTOT, 128>>>(attnF, atH, atL);

        // attended = attn @ enc_combined (batched, B = enc_comb^T), split only
        tgemm<0,0,3,2><<<dim3(4, 4, 8), 256, GSMEM>>>(
            atH, atL, etH, etL, nullptr, nullptr, nullptr, adH, adL,
            512, 512, 512, TS, TS, TS);

        // conv_input = ((attended@e2h + b + glu)*S + conv_input)*S -> xpad (fp32+split)
        tgemm<0,1,2,1><<<dim3(8, 32), 256, GSMEM>>>(
            adH, adL, w3H, w3L, attn_e2h_b, gluF, xpadF, xpH, xpL,
            1024, 512, 512, 0, 0, 0);
    }

    // conv_output = conv_input(token map) @ hid2emb + b, split only
    tgemm<2,0,0,2><<<dim3(4, 32), 256, GSMEM>>>(
        xpH, xpL, w4H, w4L, hid2emb_b, nullptr, nullptr, coH, coL,
        512, 1024, 1024, 0, 0, 0);

    // logits = conv_output @ fc + b, fp32 -> d_out
    tgemm<0,0,0,0><<<dim3(250, 32), 256, GSMEM>>>(
        coH, coL, wfH, wfL, fc_b, nullptr, out, nullptr, nullptr,
        32000, 512, 512, 0, 0, 0);
}